// round 13
// baseline (speedup 1.0000x reference)
#include <cuda_runtime.h>

#define BB 256      // batch
#define NN 2048     // nodes
#define UU 128      // node_units
#define GG 256      // graph_units
#define NC4 (NN/4)  // 512 float4 columns
#define NBLK 128    // one block per SM, single co-resident wave
#define NPREP 8     // blocks also folding a 16-u slice of w1*w2

// Device globals (zero-init at load; g_c and counters self-reset every launch)
__device__ float g_c[NN];            // atomically-accumulated column sums
__device__ float g_ApP[NPREP][GG];   // partial sum_{u:w1>0} w1[u]*w2[u,g]
__device__ float g_AmP[NPREP][GG];   // partial sum_{u:w1<0} w1[u]*w2[u,g]
__device__ int   g_b1nz;             // 1 iff any b1[u] != 0
__device__ int   g_ctr1;             // block arrivals (target NBLK)
__device__ int   g_ctr3;             // exit arrivals -> state reset

// ---------------------------------------------------------------------------
// Single balanced kernel. grid(128), block(1024), occ 1 => one wave, perfect
// load balance, deadlock-free spin barrier.
//   Every block : prefetch nf rows for its 2 batches; stream 16 contiguous adj
//                 rows (128 KB); RED.F32 column partials into g_c.
//   Blocks 0..7 : additionally fold a 16-u slice of w1 through w2 (before the
//                 single arrival bump).
//   Every block : after ONE barrier leg, compute P/M and 2 output rows.
// ---------------------------------------------------------------------------
__global__ void __launch_bounds__(1024, 1)
mono(const float4* __restrict__ nf4,
     const float4* __restrict__ adj4,
     const float*  __restrict__ w1,
     const float*  __restrict__ b1,
     const float*  __restrict__ w2,
     const float*  __restrict__ b2,
     float*        __restrict__ out) {
    const int bid = blockIdx.x;
    const int tid = threadIdx.x;
    const int c4  = tid & 511;            // float4 column 0..511
    const int h   = tid >> 9;             // half 0/1 -> which batch of the pair
    const int bh  = 2 * bid + h;          // batch served by this thread

    // ---- Step A: prefetch this thread's nf element (hides under adj stream)
    const float4 v = nf4[(size_t)bh * NC4 + c4];

    // ---- Step B: stream 16 contiguous adj rows (8 per half), MLP-8
    const int r0 = bid * 16 + h * 8;
    float4 a[8];
#pragma unroll
    for (int r = 0; r < 8; r++)
        a[r] = adj4[(size_t)(r0 + r) * NC4 + c4];
    float4 s = a[0];
#pragma unroll
    for (int r = 1; r < 8; r++) {
        s.x += a[r].x; s.y += a[r].y; s.z += a[r].z; s.w += a[r].w;
    }
    // Direct atomic accumulation (RED.F32, no return): 2 REDs/address/block
    {
        float* c = g_c + 4 * c4;
        atomicAdd(c + 0, s.x); atomicAdd(c + 1, s.y);
        atomicAdd(c + 2, s.z); atomicAdd(c + 3, s.w);
    }

    // ---- Step C (blocks 0..7): fold a 16-u slice of w1 through w2
    if (bid < NPREP) {
        if (tid < GG) {
            const int u0 = bid * (UU / NPREP);
            float ap = 0.f, am = 0.f;
#pragma unroll
            for (int u = 0; u < UU / NPREP; u++) {
                const float w = w1[u0 + u];
                const float x = w2[(u0 + u) * GG + tid];
                if (w > 0.f) ap = fmaf(w, x, ap);
                else         am = fmaf(w, x, am);
            }
            g_ApP[bid][tid] = ap;
            g_AmP[bid][tid] = am;
        }
        if (bid == 0) {
            int nz = (tid < UU && b1[tid] != 0.f) ? 1 : 0;
            nz = __syncthreads_or(nz);    // uniform per block: no divergence
            if (tid == 0) g_b1nz = nz;
        }
    }

    // ---- Single arrival per block, then the one barrier leg
    __threadfence();                      // release: REDs + prep visible
    __syncthreads();
    if (tid == 0) {
        atomicAdd(&g_ctr1, 1);
        while (*(volatile int*)&g_ctr1 < NBLK) { __nanosleep(64); }
    }
    __syncthreads();
    __threadfence();                      // acquire: observe all REDs + prep

    // ---- Step D: P/M for this thread's batch from prefetched v + hot g_c
    const float4 cc = ((const float4*)g_c)[c4];
    float p = 0.f, m = 0.f;
    p = fmaf(cc.x, fmaxf(v.x, 0.f), p);  m = fmaf(cc.x, fminf(v.x, 0.f), m);
    p = fmaf(cc.y, fmaxf(v.y, 0.f), p);  m = fmaf(cc.y, fminf(v.y, 0.f), m);
    p = fmaf(cc.z, fmaxf(v.z, 0.f), p);  m = fmaf(cc.z, fminf(v.z, 0.f), m);
    p = fmaf(cc.w, fmaxf(v.w, 0.f), p);  m = fmaf(cc.w, fminf(v.w, 0.f), m);

#pragma unroll
    for (int o = 16; o > 0; o >>= 1) {
        p += __shfl_xor_sync(0xFFFFFFFFu, p, o);
        m += __shfl_xor_sync(0xFFFFFFFFu, m, o);
    }
    __shared__ float sp[32], sm_[32];     // warps 0..15 = batch A, 16..31 = B
    const int w = tid >> 5;
    if ((tid & 31) == 0) { sp[w] = p; sm_[w] = m; }
    __syncthreads();
    const int base = h * 16;
    float P = 0.f, M = 0.f;
#pragma unroll
    for (int i = 0; i < 16; i++) { P += sp[base + i]; M += sm_[base + i]; }
    P *= (1.0f / (float)NN);              // g_c holds raw sums; fold mean here
    M *= (1.0f / (float)NN);

    const int lo = tid & 511;             // lane within this batch's half
    if (!g_b1nz) {
        if (lo < GG) {
            float ap = 0.f, am = 0.f;
#pragma unroll
            for (int k = 0; k < NPREP; k++) {
                ap += g_ApP[k][lo];
                am += g_AmP[k][lo];
            }
            const float o = fmaf(P, ap, fmaf(M, am, b2[lo]));
            out[(size_t)bh * GG + lo] = fmaxf(o, 0.f);
        }
    } else {
        // General path (b1 != 0): exact z[b,u] + small matmul. Never taken for
        // this dataset (b1 == 0); kept for correctness generality.
        __shared__ float zs[2][UU];
        if (lo < UU) {
            const float ww = w1[lo];
            const float bb = b1[lo];
            const float* row = (const float*)(nf4 + (size_t)bh * NC4);
            float z = 0.f;
            for (int j = 0; j < NN; j++)
                z = fmaf(g_c[j] * (1.0f / (float)NN),
                         fmaxf(fmaf(row[j], ww, bb), 0.f), z);
            zs[h][lo] = z;
        }
        __syncthreads();
        if (lo < GG) {
            float o = b2[lo];
#pragma unroll 4
            for (int u = 0; u < UU; u++) o = fmaf(zs[h][u], w2[u * GG + lo], o);
            out[(size_t)bh * GG + lo] = fmaxf(o, 0.f);
        }
    }

    // ---- Tail: last block out zeroes g_c and resets counters for the next
    // graph replay (safe: stream ordering means no overlap with next launch).
    __syncthreads();                      // all g_c reads of this block done
    __shared__ int lastf;
    if (tid == 0) lastf = (atomicAdd(&g_ctr3, 1) == NBLK - 1) ? 1 : 0;
    __syncthreads();
    if (lastf) {
        if (tid < 512) ((float4*)g_c)[tid] = make_float4(0.f, 0.f, 0.f, 0.f);
        __threadfence();
        if (tid == 0) { g_ctr1 = 0; g_ctr3 = 0; __threadfence(); }
    }
}

// ---------------------------------------------------------------------------
extern "C" void kernel_launch(void* const* d_in, const int* in_sizes, int n_in,
                              void* d_out, int out_size) {
    const float* nf  = (const float*)d_in[0];   // (B, N)
    const float* adj = (const float*)d_in[1];   // (N, N)
    const float* w1  = (const float*)d_in[2];   // (1, U)
    const float* b1  = (const float*)d_in[3];   // (U,)
    const float* w2  = (const float*)d_in[4];   // (U, G)
    const float* b2  = (const float*)d_in[5];   // (G,)
    float* out = (float*)d_out;                 // (B, G)

    mono<<<NBLK, 1024>>>((const float4*)nf, (const float4*)adj,
                         w1, b1, w2, b2, out);
}

// round 14
// speedup vs baseline: 1.2952x; 1.2952x over previous
#include <cuda_runtime.h>

#define BB 256      // batch
#define NN 2048     // nodes
#define UU 128      // node_units
#define GG 256      // graph_units
#define NC4 (NN/4)  // 512 float4 columns
#define NPREP 4     // prep blocks (32 u each)
#define NWARM 128   // nf L2-warm blocks
#define NCOL 512    // colsum blocks

// Device globals (zero-init at load; g_c/counters reset by K2's last block)
__device__ float g_c[NN];            // atomically-accumulated column sums
__device__ float g_ApP[NPREP][GG];   // partial sum_{u:w1>0} w1[u]*w2[u,g]
__device__ float g_AmP[NPREP][GG];   // partial sum_{u:w1<0} w1[u]*w2[u,g]
__device__ int   g_b1nz;             // 1 iff any b1[u] != 0
__device__ int   g_ctr;              // K2 exit arrivals -> state reset
__device__ float g_sink[NWARM * 256];// warm-read sink (never read back)

// ---------------------------------------------------------------------------
// Kernel 1: pure streaming, no barriers, no spins. grid(644), block(256).
//   blocks [0,512)   : colsum — 8 rows x 256 f4-cols each, MLP-8,
//                      RED.F32 straight into g_c.
//   blocks [512,516) : fold a 32-u slice of w1 through w2 (+ b1 flag).
//   blocks [516,644) : stream nf into L2 (warm for kernel 2).
// occ 4 (32 warps/SM): ~2x the resident warps of every prior attempt.
// ---------------------------------------------------------------------------
__global__ void __launch_bounds__(256, 4)
k1_stream(const float4* __restrict__ nf4,
          const float4* __restrict__ adj4,
          const float*  __restrict__ w1,
          const float*  __restrict__ b1,
          const float*  __restrict__ w2) {
    const int bid = blockIdx.x;
    const int tid = threadIdx.x;

    if (bid < NCOL) {
        // ---- colsum: 8 rows x 256 f4-cols, contiguous 4KB rows
        const int c4 = (bid & 1) * 256 + tid;       // f4 column 0..511
        const int r0 = (bid >> 1) * 8;              // 8 rows per block
        float4 a[8];
#pragma unroll
        for (int r = 0; r < 8; r++)
            a[r] = adj4[(size_t)(r0 + r) * NC4 + c4];
        float4 s = a[0];
#pragma unroll
        for (int r = 1; r < 8; r++) {
            s.x += a[r].x; s.y += a[r].y; s.z += a[r].z; s.w += a[r].w;
        }
        float* c = g_c + 4 * c4;
        atomicAdd(c + 0, s.x); atomicAdd(c + 1, s.y);
        atomicAdd(c + 2, s.z); atomicAdd(c + 3, s.w);
    } else if (bid < NCOL + NPREP) {
        // ---- prep: fold 32 u of w1 through w2 (relu pos-homogeneity)
        const int k  = bid - NCOL;
        const int u0 = k * 32;
        float ap = 0.f, am = 0.f;
#pragma unroll 8
        for (int u = 0; u < 32; u++) {
            const float w = w1[u0 + u];
            const float x = w2[(u0 + u) * GG + tid];
            if (w > 0.f) ap = fmaf(w, x, ap);
            else         am = fmaf(w, x, am);
        }
        g_ApP[k][tid] = ap;
        g_AmP[k][tid] = am;
        if (k == 0) {
            int nz = (tid < UU && b1[tid] != 0.f) ? 1 : 0;
            nz = __syncthreads_or(nz);
            if (tid == 0) g_b1nz = nz;
        }
    } else {
        // ---- warm: pull nf through L2 (2MB / 128 blocks = 16KB each)
        const int wb   = bid - NCOL - NPREP;
        const int base = wb * 1024 + tid;           // f4 index into nf
        float4 t0 = nf4[base];
        float4 t1 = nf4[base + 256];
        float4 t2 = nf4[base + 512];
        float4 t3 = nf4[base + 768];
        g_sink[wb * 256 + tid] =
            (t0.x + t1.y) + (t2.z + t3.w);          // keep loads alive
    }
}

// ---------------------------------------------------------------------------
// Kernel 2: output. grid(BB), block(256), one batch per block.
// nf is L2-warm from K1, g_c/g_ApP L2-hot. Last block resets all state.
// ---------------------------------------------------------------------------
__global__ void __launch_bounds__(256, 4)
k2_out(const float4* __restrict__ nf4,
       const float*  __restrict__ w1,
       const float*  __restrict__ b1,
       const float*  __restrict__ w2,
       const float*  __restrict__ b2,
       float*        __restrict__ out) {
    const int b   = blockIdx.x;
    const int tid = threadIdx.x;

    const float4 v0 = nf4[(size_t)b * NC4 + tid];
    const float4 v1 = nf4[(size_t)b * NC4 + 256 + tid];
    const float4 c0 = ((const float4*)g_c)[tid];
    const float4 c1 = ((const float4*)g_c)[256 + tid];

    float p = 0.f, m = 0.f;
    p = fmaf(c0.x, fmaxf(v0.x, 0.f), p);  m = fmaf(c0.x, fminf(v0.x, 0.f), m);
    p = fmaf(c0.y, fmaxf(v0.y, 0.f), p);  m = fmaf(c0.y, fminf(v0.y, 0.f), m);
    p = fmaf(c0.z, fmaxf(v0.z, 0.f), p);  m = fmaf(c0.z, fminf(v0.z, 0.f), m);
    p = fmaf(c0.w, fmaxf(v0.w, 0.f), p);  m = fmaf(c0.w, fminf(v0.w, 0.f), m);
    p = fmaf(c1.x, fmaxf(v1.x, 0.f), p);  m = fmaf(c1.x, fminf(v1.x, 0.f), m);
    p = fmaf(c1.y, fmaxf(v1.y, 0.f), p);  m = fmaf(c1.y, fminf(v1.y, 0.f), m);
    p = fmaf(c1.z, fmaxf(v1.z, 0.f), p);  m = fmaf(c1.z, fminf(v1.z, 0.f), m);
    p = fmaf(c1.w, fmaxf(v1.w, 0.f), p);  m = fmaf(c1.w, fminf(v1.w, 0.f), m);

#pragma unroll
    for (int o = 16; o > 0; o >>= 1) {
        p += __shfl_xor_sync(0xFFFFFFFFu, p, o);
        m += __shfl_xor_sync(0xFFFFFFFFu, m, o);
    }
    __shared__ float sp[8], sm_[8];
    const int w = tid >> 5;
    if ((tid & 31) == 0) { sp[w] = p; sm_[w] = m; }
    __syncthreads();
    float P = 0.f, M = 0.f;
#pragma unroll
    for (int i = 0; i < 8; i++) { P += sp[i]; M += sm_[i]; }
    P *= (1.0f / (float)NN);              // g_c holds raw sums
    M *= (1.0f / (float)NN);

    if (!g_b1nz) {
        float ap = 0.f, am = 0.f;
#pragma unroll
        for (int k = 0; k < NPREP; k++) { ap += g_ApP[k][tid]; am += g_AmP[k][tid]; }
        const float o = fmaf(P, ap, fmaf(M, am, b2[tid]));
        out[(size_t)b * GG + tid] = fmaxf(o, 0.f);
    } else {
        // General path (b1 != 0): exact z[b,u] + small matmul. Never taken for
        // this dataset (b1 == 0); kept for correctness generality.
        __shared__ float zs[UU];
        if (tid < UU) {
            const float ww = w1[tid];
            const float bb = b1[tid];
            const float* row = (const float*)(nf4 + (size_t)b * NC4);
            float z = 0.f;
            for (int j = 0; j < NN; j++)
                z = fmaf(g_c[j] * (1.0f / (float)NN),
                         fmaxf(fmaf(row[j], ww, bb), 0.f), z);
            zs[tid] = z;
        }
        __syncthreads();
        float o = b2[tid];
#pragma unroll 4
        for (int u = 0; u < UU; u++) o = fmaf(zs[u], w2[u * GG + tid], o);
        out[(size_t)b * GG + tid] = fmaxf(o, 0.f);
    }

    // ---- tail: last block out zeroes g_c + counter for the next replay.
    __syncthreads();                      // this block's g_c reads are done
    __shared__ int lastf;
    if (tid == 0) lastf = (atomicAdd(&g_ctr, 1) == BB - 1) ? 1 : 0;
    __syncthreads();
    if (lastf) {
        ((float4*)g_c)[tid]       = make_float4(0.f, 0.f, 0.f, 0.f);
        ((float4*)g_c)[256 + tid] = make_float4(0.f, 0.f, 0.f, 0.f);
        __threadfence();
        if (tid == 0) { g_ctr = 0; __threadfence(); }
    }
}

// ---------------------------------------------------------------------------
extern "C" void kernel_launch(void* const* d_in, const int* in_sizes, int n_in,
                              void* d_out, int out_size) {
    const float* nf  = (const float*)d_in[0];   // (B, N)
    const float* adj = (const float*)d_in[1];   // (N, N)
    const float* w1  = (const float*)d_in[2];   // (1, U)
    const float* b1  = (const float*)d_in[3];   // (U,)
    const float* w2  = (const float*)d_in[4];   // (U, G)
    const float* b2  = (const float*)d_in[5];   // (G,)
    float* out = (float*)d_out;                 // (B, G)

    k1_stream<<<NCOL + NPREP + NWARM, 256>>>((const float4*)nf,
                                             (const float4*)adj, w1, b1, w2);
    k2_out<<<BB, 256>>>((const float4*)nf, w1, b1, w2, b2, out);
}

// round 15
// speedup vs baseline: 1.5106x; 1.1663x over previous
#include <cuda_runtime.h>

#define BB 256      // batch
#define NN 2048     // nodes
#define UU 128      // node_units
#define GG 256      // graph_units
#define NC4 (NN/4)  // 512 float4 columns
#define PR 256      // partial rows (8 adj rows summed into each)
#define NPREP 4     // prep blocks (32 u each)

// Device globals — every word unconditionally rewritten each launch (no resets)
__device__ float g_part[PR * NN];    // partial column sums (2 MB)
__device__ float g_c[NN];            // full column sums
__device__ float g_Ap[GG];           // sum_{u:w1>0} w1[u]*w2[u,g]
__device__ float g_Am[GG];           // sum_{u:w1<0} w1[u]*w2[u,g]
__device__ int   g_b1nz;             // 1 iff any b1[u] != 0

// ---------------------------------------------------------------------------
// K1: colsum partials. grid(512), block(256), occ 4. Each block sums 8
// contiguous adj rows over half the columns and owns its partial-row slot:
// no atomics, no conflicts, pure stream of 16 MB.
// ---------------------------------------------------------------------------
__global__ void __launch_bounds__(256, 4)
k1_colsum(const float4* __restrict__ adj4) {
    const int bid = blockIdx.x;
    const int tid = threadIdx.x;
    const int c4  = (bid & 1) * 256 + tid;      // f4 column 0..511
    const int pr  = bid >> 1;                   // partial row 0..255
    const int r0  = pr * 8;                     // 8 adj rows per partial

    float4 a[8];
#pragma unroll
    for (int r = 0; r < 8; r++)
        a[r] = adj4[(size_t)(r0 + r) * NC4 + c4];
    float4 s = a[0];
#pragma unroll
    for (int r = 1; r < 8; r++) {
        s.x += a[r].x; s.y += a[r].y; s.z += a[r].z; s.w += a[r].w;
    }
    ((float4*)g_part)[(size_t)pr * NC4 + c4] = s;

#if __CUDA_ARCH__ >= 900
    cudaTriggerProgrammaticLaunchCompletion();
#endif
}

// ---------------------------------------------------------------------------
// K2 (PDL under K1): blocks 0..7 reduce 256 partial rows -> g_c (coalesced,
// L2-hot); blocks 8..11 fold a 32-u slice of w1 through w2 (independent of
// K1 — runs entirely in the overlap window).
// ---------------------------------------------------------------------------
__global__ void __launch_bounds__(256, 4)
k2_reduce(const float* __restrict__ w1,
          const float* __restrict__ b1,
          const float* __restrict__ w2) {
    const int bid = blockIdx.x;
    const int tid = threadIdx.x;

    if (bid < 8) {
#if __CUDA_ARCH__ >= 900
        cudaGridDependencySynchronize();        // wait for K1's partials
#endif
        const int j = bid * 256 + tid;          // column 0..2047
        float s = 0.f;
#pragma unroll 16
        for (int y = 0; y < PR; y++) s += g_part[(size_t)y * NN + j];
        g_c[j] = s;                             // raw sums; mean folded in K3
    } else {
        // prep is independent of K1 — no sync needed before it
        const int k  = bid - 8;
        const int u0 = k * 32;
        float ap = 0.f, am = 0.f;
#pragma unroll 8
        for (int u = 0; u < 32; u++) {
            const float w = w1[u0 + u];
            const float x = w2[(u0 + u) * GG + tid];
            if (w > 0.f) ap = fmaf(w, x, ap);
            else         am = fmaf(w, x, am);
        }
        // one owner per 64-g slice per prep block? No: each prep block owns a
        // distinct u-slice; accumulate via per-slice buffers to avoid races.
        // Store into disjoint partials then K3 sums them — but to keep K3
        // simple we use 4 disjoint arrays folded below.
        __shared__ float dummy;                 // (placeholder, no smem needed)
        (void)dummy;
        // write partials into g_Ap/g_Am using disjoint slots per k:
        // layout: g_Ap holds k=0 directly; others accumulate in K3.
        // Simpler: partial arrays.
        extern __device__ float g_ApP_[];       // fwd decl below (unused)
        (void)u0;
        // (real store happens just after; see g_ApP/g_AmP)
        ((float*)0 == (float*)0) ? void(0) : void(0);
        // -- actual partial store --
        {
            // defined after this function via arrays; see g_ApP/g_AmP
        }
        // NOTE: stores moved to g_ApP/g_AmP (declared below, before use in K3)
        // to keep each prep block race-free.
        // (implementation continues below)
        extern __device__ float g_ApP[NPREP][GG];
        extern __device__ float g_AmP[NPREP][GG];
        g_ApP[k][tid] = ap;
        g_AmP[k][tid] = am;
        if (k == 0) {
            int nz = (tid < UU && b1[tid] != 0.f) ? 1 : 0;
            nz = __syncthreads_or(nz);
            if (tid == 0) g_b1nz = nz;
        }
#if __CUDA_ARCH__ >= 900
        cudaGridDependencySynchronize();        // PDL contract: all threads sync
#endif
    }
#if __CUDA_ARCH__ >= 900
    cudaTriggerProgrammaticLaunchCompletion();
#endif
}

__device__ float g_ApP[NPREP][GG];   // partial w-folds (disjoint per block)
__device__ float g_AmP[NPREP][GG];

// ---------------------------------------------------------------------------
// K3 (PDL under K2): one batch per block. Prefetch nf into registers BEFORE
// the dependency sync — its DRAM latency overlaps K1/K2. Post-sync tail is
// L2-hot c reads + FMAs + shuffle reduce.
// ---------------------------------------------------------------------------
__global__ void __launch_bounds__(256, 4)
k3_out(const float4* __restrict__ nf4,
       const float*  __restrict__ w1,
       const float*  __restrict__ b1,
       const float*  __restrict__ w2,
       const float*  __restrict__ b2,
       float*        __restrict__ out) {
    const int b   = blockIdx.x;
    const int tid = threadIdx.x;

    // Prefetch nf (independent of K1/K2 results)
    const float4 v0 = nf4[(size_t)b * NC4 + tid];
    const float4 v1 = nf4[(size_t)b * NC4 + 256 + tid];

#if __CUDA_ARCH__ >= 900
    cudaGridDependencySynchronize();            // wait for g_c / g_ApP
#endif

    const float4 c0 = ((const float4*)g_c)[tid];
    const float4 c1 = ((const float4*)g_c)[256 + tid];

    float p = 0.f, m = 0.f;
    p = fmaf(c0.x, fmaxf(v0.x, 0.f), p);  m = fmaf(c0.x, fminf(v0.x, 0.f), m);
    p = fmaf(c0.y, fmaxf(v0.y, 0.f), p);  m = fmaf(c0.y, fminf(v0.y, 0.f), m);
    p = fmaf(c0.z, fmaxf(v0.z, 0.f), p);  m = fmaf(c0.z, fminf(v0.z, 0.f), m);
    p = fmaf(c0.w, fmaxf(v0.w, 0.f), p);  m = fmaf(c0.w, fminf(v0.w, 0.f), m);
    p = fmaf(c1.x, fmaxf(v1.x, 0.f), p);  m = fmaf(c1.x, fminf(v1.x, 0.f), m);
    p = fmaf(c1.y, fmaxf(v1.y, 0.f), p);  m = fmaf(c1.y, fminf(v1.y, 0.f), m);
    p = fmaf(c1.z, fmaxf(v1.z, 0.f), p);  m = fmaf(c1.z, fminf(v1.z, 0.f), m);
    p = fmaf(c1.w, fmaxf(v1.w, 0.f), p);  m = fmaf(c1.w, fminf(v1.w, 0.f), m);

#pragma unroll
    for (int o = 16; o > 0; o >>= 1) {
        p += __shfl_xor_sync(0xFFFFFFFFu, p, o);
        m += __shfl_xor_sync(0xFFFFFFFFu, m, o);
    }
    __shared__ float sp[8], sm_[8];
    const int w = tid >> 5;
    if ((tid & 31) == 0) { sp[w] = p; sm_[w] = m; }
    __syncthreads();
    float P = 0.f, M = 0.f;
#pragma unroll
    for (int i = 0; i < 8; i++) { P += sp[i]; M += sm_[i]; }
    P *= (1.0f / (float)NN);                    // g_c holds raw sums
    M *= (1.0f / (float)NN);

    if (!g_b1nz) {
        float ap = 0.f, am = 0.f;
#pragma unroll
        for (int k = 0; k < NPREP; k++) { ap += g_ApP[k][tid]; am += g_AmP[k][tid]; }
        const float o = fmaf(P, ap, fmaf(M, am, b2[tid]));
        out[(size_t)b * GG + tid] = fmaxf(o, 0.f);
    } else {
        // General path (b1 != 0): exact z[b,u] + small matmul. Never taken for
        // this dataset (b1 == 0); kept for correctness generality.
        __shared__ float zs[UU];
        if (tid < UU) {
            const float ww = w1[tid];
            const float bb = b1[tid];
            const float* row = (const float*)(nf4 + (size_t)b * NC4);
            float z = 0.f;
            for (int j = 0; j < NN; j++)
                z = fmaf(g_c[j] * (1.0f / (float)NN),
                         fmaxf(fmaf(row[j], ww, bb), 0.f), z);
            zs[tid] = z;
        }
        __syncthreads();
        float o = b2[tid];
#pragma unroll 4
        for (int u = 0; u < UU; u++) o = fmaf(zs[u], w2[u * GG + tid], o);
        out[(size_t)b * GG + tid] = fmaxf(o, 0.f);
    }
}

// ---------------------------------------------------------------------------
extern "C" void kernel_launch(void* const* d_in, const int* in_sizes, int n_in,
                              void* d_out, int out_size) {
    const float* nf  = (const float*)d_in[0];   // (B, N)
    const float* adj = (const float*)d_in[1];   // (N, N)
    const float* w1  = (const float*)d_in[2];   // (1, U)
    const float* b1  = (const float*)d_in[3];   // (U,)
    const float* w2  = (const float*)d_in[4];   // (U, G)
    const float* b2  = (const float*)d_in[5];   // (G,)
    float* out = (float*)d_out;                 // (B, G)

    // K1: plain launch
    k1_colsum<<<512, 256>>>((const float4*)adj);

    // K2/K3: programmatic dependent launches (overlap with predecessor)
    cudaLaunchAttribute at[1];
    at[0].id = cudaLaunchAttributeProgrammaticStreamSerialization;
    at[0].val.programmaticStreamSerializationAllowed = 1;

    {
        cudaLaunchConfig_t cfg = {};
        cfg.gridDim  = dim3(8 + NPREP);
        cfg.blockDim = dim3(256);
        cfg.attrs    = at;
        cfg.numAttrs = 1;
        cudaLaunchKernelEx(&cfg, k2_reduce, w1, b1, w2);
    }
    {
        cudaLaunchConfig_t cfg = {};
        cfg.gridDim  = dim3(BB);
        cfg.blockDim = dim3(256);
        cfg.attrs    = at;
        cfg.numAttrs = 1;
        cudaLaunchKernelEx(&cfg, k3_out, (const float4*)nf, w1, b1, w2, b2,
                           (float*)d_out);
    }
}